// round 2
// baseline (speedup 1.0000x reference)
#include <cuda_runtime.h>
#include <math.h>

#define Bc 4
#define Sc 2048
#define Ec 1024
#define Hc 16
#define Dc 64
#define Mtot (Bc*Sc)   // 8192

// Scratch (static device globals: allocation-free)
__device__ float g_Q[(size_t)Bc*Hc*Sc*Dc];
__device__ float g_K[(size_t)Bc*Hc*Sc*Dc];
__device__ float g_V[(size_t)Bc*Hc*Sc*Dc];
__device__ float g_A[(size_t)Bc*Sc*Ec];

// ---------------- GEMM: C[M,1024] = A[M,1024] @ W[1024,1024] + bias --------
// 128x128 tile, BK=8, 256 threads, 8x8 per thread.
#define GBM 128
#define GBN 128
#define GBK 8

__global__ __launch_bounds__(256, 2) void gemm_kernel(
    const float* __restrict__ A, const float* __restrict__ W,
    const float* __restrict__ bias, float* __restrict__ C, int split)
{
    __shared__ float As[GBK][GBM];
    __shared__ float Ws[GBK][GBN];
    const int tid = threadIdx.x;
    const int tx = tid & 15, ty = tid >> 4;
    const int bm = blockIdx.y * GBM;
    const int bn = blockIdx.x * GBN;

    const int arow = tid >> 1;        // 0..127
    const int acol = (tid & 1) * 4;   // 0 or 4
    const int wrow = tid >> 5;        // 0..7
    const int wcol = (tid & 31) * 4;  // 0..124

    float acc[8][8];
    #pragma unroll
    for (int i = 0; i < 8; i++)
        #pragma unroll
        for (int j = 0; j < 8; j++) acc[i][j] = 0.f;

    for (int k0 = 0; k0 < Ec; k0 += GBK) {
        float4 a4 = *(const float4*)&A[(size_t)(bm + arow) * Ec + k0 + acol];
        As[acol + 0][arow] = a4.x; As[acol + 1][arow] = a4.y;
        As[acol + 2][arow] = a4.z; As[acol + 3][arow] = a4.w;
        *(float4*)&Ws[wrow][wcol] =
            *(const float4*)&W[(size_t)(k0 + wrow) * Ec + bn + wcol];
        __syncthreads();
        #pragma unroll
        for (int kk = 0; kk < GBK; kk++) {
            float a[8], b[8];
            *(float4*)&a[0] = *(float4*)&As[kk][ty * 8];
            *(float4*)&a[4] = *(float4*)&As[kk][ty * 8 + 4];
            *(float4*)&b[0] = *(float4*)&Ws[kk][tx * 8];
            *(float4*)&b[4] = *(float4*)&Ws[kk][tx * 8 + 4];
            #pragma unroll
            for (int i = 0; i < 8; i++)
                #pragma unroll
                for (int j = 0; j < 8; j++)
                    acc[i][j] = fmaf(a[i], b[j], acc[i][j]);
        }
        __syncthreads();
    }

    #pragma unroll
    for (int i = 0; i < 8; i++) {
        const int m = bm + ty * 8 + i;
        #pragma unroll
        for (int j = 0; j < 8; j++) {
            const int n = bn + tx * 8 + j;
            float v = acc[i][j] + bias[n];
            if (split) {
                // write [B,H,S,D] layout: m = b*S+s, n = h*D+d
                const int b = m >> 11, s = m & 2047;
                const int h = n >> 6, d = n & 63;
                C[(((size_t)(b * Hc + h)) * Sc + s) * Dc + d] = v;
            } else {
                C[(size_t)m * Ec + n] = v;
            }
        }
    }
}

// ---------------- Flash attention: per (b,h), BQ=64 queries per CTA --------
__global__ __launch_bounds__(256, 2) void attn_kernel()
{
    __shared__ float Qs[Dc][64];    // transposed: [d][q]
    __shared__ float KVs[64][Dc];   // K phase: [d][k]; V phase: [k][d]
    __shared__ float Ps[64][64];    // probabilities

    const int tid = threadIdx.x;
    const int tx = tid & 15, ty = tid >> 4;
    const int qt = blockIdx.x;     // 0..31
    const int h  = blockIdx.y;
    const int b  = blockIdx.z;
    const size_t headOff = ((size_t)(b * Hc + h)) * Sc * Dc;
    const float* Qg = g_Q + headOff + (size_t)qt * 64 * Dc;
    const float* Kg = g_K + headOff;
    const float* Vg = g_V + headOff;

    // Load Q tile transposed into smem
    {
        const int q  = tid >> 2;           // 0..63
        const int d0 = (tid & 3) * 16;
        #pragma unroll
        for (int c = 0; c < 4; c++) {
            float4 v = *(const float4*)&Qg[(size_t)q * Dc + d0 + c * 4];
            Qs[d0 + c * 4 + 0][q] = v.x; Qs[d0 + c * 4 + 1][q] = v.y;
            Qs[d0 + c * 4 + 2][q] = v.z; Qs[d0 + c * 4 + 3][q] = v.w;
        }
    }

    float m[4], l[4], O[4][4];
    #pragma unroll
    for (int i = 0; i < 4; i++) {
        m[i] = -INFINITY; l[i] = 0.f;
        #pragma unroll
        for (int j = 0; j < 4; j++) O[i][j] = 0.f;
    }

    const float scale = 0.125f;  // 1/sqrt(64)

    for (int kt = 0; kt < Sc / 64; kt++) {
        __syncthreads();   // prev PV reads of KVs/Ps done; Q store visible (iter 0)
        // Load K tile transposed: KVs[d][k]
        {
            const int k  = tid >> 2;
            const int d0 = (tid & 3) * 16;
            const float* kp = Kg + (size_t)(kt * 64 + k) * Dc + d0;
            #pragma unroll
            for (int c = 0; c < 4; c++) {
                float4 v = *(const float4*)&kp[c * 4];
                KVs[d0 + c * 4 + 0][k] = v.x; KVs[d0 + c * 4 + 1][k] = v.y;
                KVs[d0 + c * 4 + 2][k] = v.z; KVs[d0 + c * 4 + 3][k] = v.w;
            }
        }
        __syncthreads();

        // S = Q K^T   (4x4 per thread: rows ty*4.., cols tx*4..)
        float s[4][4];
        #pragma unroll
        for (int i = 0; i < 4; i++)
            #pragma unroll
            for (int j = 0; j < 4; j++) s[i][j] = 0.f;

        #pragma unroll 8
        for (int d = 0; d < Dc; d++) {
            float4 qa = *(float4*)&Qs[d][ty * 4];
            float4 kb = *(float4*)&KVs[d][tx * 4];
            float a[4] = {qa.x, qa.y, qa.z, qa.w};
            float bb[4] = {kb.x, kb.y, kb.z, kb.w};
            #pragma unroll
            for (int i = 0; i < 4; i++)
                #pragma unroll
                for (int j = 0; j < 4; j++)
                    s[i][j] = fmaf(a[i], bb[j], s[i][j]);
        }

        // Online softmax (row groups = 16 lanes with same ty)
        #pragma unroll
        for (int i = 0; i < 4; i++) {
            float tmax = -INFINITY;
            #pragma unroll
            for (int j = 0; j < 4; j++) {
                s[i][j] *= scale;
                tmax = fmaxf(tmax, s[i][j]);
            }
            #pragma unroll
            for (int off = 8; off > 0; off >>= 1)
                tmax = fmaxf(tmax, __shfl_xor_sync(0xffffffffu, tmax, off));
            const float mn = fmaxf(m[i], tmax);
            const float corr = __expf(m[i] - mn);
            float rs = 0.f;
            #pragma unroll
            for (int j = 0; j < 4; j++) {
                s[i][j] = __expf(s[i][j] - mn);
                rs += s[i][j];
            }
            #pragma unroll
            for (int off = 8; off > 0; off >>= 1)
                rs += __shfl_xor_sync(0xffffffffu, rs, off);
            l[i] = l[i] * corr + rs;
            m[i] = mn;
            #pragma unroll
            for (int j = 0; j < 4; j++) O[i][j] *= corr;
            *(float4*)&Ps[ty * 4 + i][tx * 4] =
                make_float4(s[i][0], s[i][1], s[i][2], s[i][3]);
        }
        __syncthreads();   // Ps fully written, K reads done

        // Load V tile row-major: KVs[k][d]
        {
            const int k  = tid >> 2;
            const int d0 = (tid & 3) * 16;
            const float* vp = Vg + (size_t)(kt * 64 + k) * Dc + d0;
            #pragma unroll
            for (int c = 0; c < 4; c++)
                *(float4*)&KVs[k][d0 + c * 4] = *(const float4*)&vp[c * 4];
        }
        __syncthreads();

        // O += P @ V
        #pragma unroll 4
        for (int kk = 0; kk < 64; kk += 4) {
            float4 p[4];
            #pragma unroll
            for (int i = 0; i < 4; i++) p[i] = *(float4*)&Ps[ty * 4 + i][kk];
            #pragma unroll
            for (int t = 0; t < 4; t++) {
                float4 v = *(float4*)&KVs[kk + t][tx * 4];
                #pragma unroll
                for (int i = 0; i < 4; i++) {
                    const float pv = (t == 0) ? p[i].x : (t == 1) ? p[i].y
                                   : (t == 2) ? p[i].z : p[i].w;
                    O[i][0] = fmaf(pv, v.x, O[i][0]);
                    O[i][1] = fmaf(pv, v.y, O[i][1]);
                    O[i][2] = fmaf(pv, v.z, O[i][2]);
                    O[i][3] = fmaf(pv, v.w, O[i][3]);
                }
            }
        }
    }

    // Epilogue: normalize, write concat layout [B,S,E]
    #pragma unroll
    for (int i = 0; i < 4; i++) {
        const float inv = 1.f / l[i];
        const int q = qt * 64 + ty * 4 + i;
        float4 o = make_float4(O[i][0] * inv, O[i][1] * inv,
                               O[i][2] * inv, O[i][3] * inv);
        *(float4*)&g_A[((size_t)b * Sc + q) * Ec + h * Dc + tx * 4] = o;
    }
}

// ---------------------------------------------------------------------------
extern "C" void kernel_launch(void* const* d_in, const int* in_sizes, int n_in,
                              void* d_out, int out_size)
{
    const float* x  = (const float*)d_in[0];
    const float* Wq = (const float*)d_in[1];
    const float* bq = (const float*)d_in[2];
    const float* Wk = (const float*)d_in[3];
    const float* bk = (const float*)d_in[4];
    const float* Wv = (const float*)d_in[5];
    const float* bv = (const float*)d_in[6];
    const float* Wo = (const float*)d_in[7];
    const float* bo = (const float*)d_in[8];
    float* out = (float*)d_out;

    float *pQ, *pK, *pV, *pA;
    cudaGetSymbolAddress((void**)&pQ, g_Q);
    cudaGetSymbolAddress((void**)&pK, g_K);
    cudaGetSymbolAddress((void**)&pV, g_V);
    cudaGetSymbolAddress((void**)&pA, g_A);

    dim3 gg(Ec / GBN, Mtot / GBM);   // (8, 64)
    gemm_kernel<<<gg, 256>>>(x, Wq, bq, pQ, 1);
    gemm_kernel<<<gg, 256>>>(x, Wk, bk, pK, 1);
    gemm_kernel<<<gg, 256>>>(x, Wv, bv, pV, 1);
    attn_kernel<<<dim3(Sc / 64, Hc, Bc), 256>>>();
    gemm_kernel<<<gg, 256>>>(pA, Wo, bo, out, 0);
}

// round 3
// speedup vs baseline: 2.2711x; 2.2711x over previous
#include <cuda_runtime.h>
#include <math.h>
#include <stdint.h>

#define Bc 4
#define Sc 2048
#define Ec 1024
#define Hc 16
#define Dc 64
#define Mtot (Bc*Sc)   // 8192

// Scratch (static device globals: allocation-free)
__device__ float g_Q[(size_t)Bc*Hc*Sc*Dc];
__device__ float g_K[(size_t)Bc*Hc*Sc*Dc];
__device__ float g_V[(size_t)Bc*Hc*Sc*Dc];
__device__ float g_A[(size_t)Bc*Sc*Ec];

// ---- tf32 helpers ---------------------------------------------------------
__device__ __forceinline__ uint32_t f2tf(float x) {
    uint32_t u;
    asm("cvt.rna.tf32.f32 %0, %1;" : "=r"(u) : "f"(x));
    return u;
}

// D += A@B, m16n8k8 tf32, in-place accumulate
__device__ __forceinline__ void mma8(float* d, const uint32_t* a, const uint32_t* b) {
    asm volatile(
        "mma.sync.aligned.m16n8k8.row.col.f32.tf32.tf32.f32 "
        "{%0,%1,%2,%3}, {%4,%5,%6,%7}, {%8,%9}, {%0,%1,%2,%3};"
        : "+f"(d[0]), "+f"(d[1]), "+f"(d[2]), "+f"(d[3])
        : "r"(a[0]), "r"(a[1]), "r"(a[2]), "r"(a[3]), "r"(b[0]), "r"(b[1]));
}

// ---------------- GEMM: C[M,1024] = A[M,1024] @ W[1024,1024] + bias --------
// 128x128 tile, BK=32, 256 threads (8 warps), warp tile 64x32.
#define GBM 128
#define GBN 128
#define GBK 32
#define ASTR 36
#define WSTR 132

__global__ __launch_bounds__(256, 2) void gemm_tc(
    const float* __restrict__ A, const float* __restrict__ W,
    const float* __restrict__ bias, float* __restrict__ C, int split)
{
    __shared__ uint32_t As[GBM][ASTR];   // [m][k]
    __shared__ uint32_t Ws[GBK][WSTR];   // [k][n]

    const int tid  = threadIdx.x;
    const int lane = tid & 31, warp = tid >> 5;
    const int g = lane >> 2, tg = lane & 3;
    const int wm = warp >> 2, wn = warp & 3;          // 2 x 4 warp grid
    const int bm = blockIdx.y * GBM, bn = blockIdx.x * GBN;

    float acc[4][4][4];
    #pragma unroll
    for (int mt = 0; mt < 4; mt++)
        #pragma unroll
        for (int nt = 0; nt < 4; nt++)
            #pragma unroll
            for (int i = 0; i < 4; i++) acc[mt][nt][i] = 0.f;

    const int arow  = tid >> 1;          // 0..127
    const int acol0 = (tid & 1) * 16;    // 0 / 16
    const int wrow  = tid >> 3;          // 0..31
    const int wcol0 = (tid & 7) * 16;    // 0..112

    for (int k0 = 0; k0 < Ec; k0 += GBK) {
        #pragma unroll
        for (int c = 0; c < 4; c++) {
            float4 v = *(const float4*)&A[(size_t)(bm + arow) * Ec + k0 + acol0 + c * 4];
            As[arow][acol0 + c * 4 + 0] = f2tf(v.x);
            As[arow][acol0 + c * 4 + 1] = f2tf(v.y);
            As[arow][acol0 + c * 4 + 2] = f2tf(v.z);
            As[arow][acol0 + c * 4 + 3] = f2tf(v.w);
        }
        #pragma unroll
        for (int c = 0; c < 4; c++) {
            float4 v = *(const float4*)&W[(size_t)(k0 + wrow) * Ec + bn + wcol0 + c * 4];
            Ws[wrow][wcol0 + c * 4 + 0] = f2tf(v.x);
            Ws[wrow][wcol0 + c * 4 + 1] = f2tf(v.y);
            Ws[wrow][wcol0 + c * 4 + 2] = f2tf(v.z);
            Ws[wrow][wcol0 + c * 4 + 3] = f2tf(v.w);
        }
        __syncthreads();

        #pragma unroll
        for (int ks = 0; ks < 4; ks++) {
            uint32_t af[4][4], bf[4][2];
            #pragma unroll
            for (int mt = 0; mt < 4; mt++) {
                const int r = wm * 64 + mt * 16 + g;
                af[mt][0] = As[r][ks * 8 + tg];
                af[mt][1] = As[r + 8][ks * 8 + tg];
                af[mt][2] = As[r][ks * 8 + tg + 4];
                af[mt][3] = As[r + 8][ks * 8 + tg + 4];
            }
            #pragma unroll
            for (int nt = 0; nt < 4; nt++) {
                const int cb = wn * 32 + nt * 8 + g;
                bf[nt][0] = Ws[ks * 8 + tg][cb];
                bf[nt][1] = Ws[ks * 8 + tg + 4][cb];
            }
            #pragma unroll
            for (int mt = 0; mt < 4; mt++)
                #pragma unroll
                for (int nt = 0; nt < 4; nt++)
                    mma8(acc[mt][nt], af[mt], bf[nt]);
        }
        __syncthreads();
    }

    #pragma unroll
    for (int mt = 0; mt < 4; mt++) {
        #pragma unroll
        for (int half = 0; half < 2; half++) {
            const int m = bm + wm * 64 + mt * 16 + g + half * 8;
            #pragma unroll
            for (int nt = 0; nt < 4; nt++) {
                const int n = bn + wn * 32 + nt * 8 + 2 * tg;
                float v0 = acc[mt][nt][half * 2 + 0] + bias[n];
                float v1 = acc[mt][nt][half * 2 + 1] + bias[n + 1];
                if (split) {
                    const int b = m >> 11, s = m & 2047;
                    const int h = n >> 6, d = n & 63;
                    *(float2*)&C[(((size_t)(b * Hc + h)) * Sc + s) * Dc + d] =
                        make_float2(v0, v1);
                } else {
                    *(float2*)&C[(size_t)m * Ec + n] = make_float2(v0, v1);
                }
            }
        }
    }
}

// ---------------- Flash attention (tf32 mma): 128 q / CTA, 8 warps ---------
#define AQ 128
#define QSTR 68

__global__ __launch_bounds__(256, 2) void attn_tc(
    const float* __restrict__ Qg_, const float* __restrict__ Kg_,
    const float* __restrict__ Vg_, float* __restrict__ Ag_)
{
    extern __shared__ uint32_t sm[];
    uint32_t (*Qs)[QSTR] = (uint32_t(*)[QSTR])(sm);                 // [128][68]
    uint32_t (*Kt)[QSTR] = (uint32_t(*)[QSTR])(sm + 128 * QSTR);    // [d][kv]
    uint32_t (*Vs)[QSTR] = (uint32_t(*)[QSTR])(sm + 192 * QSTR);    // [kv][d]
    uint32_t (*Ps)[QSTR] = (uint32_t(*)[QSTR])(sm + 256 * QSTR);    // [q][kv]

    const int tid  = threadIdx.x;
    const int lane = tid & 31, warp = tid >> 5;
    const int g = lane >> 2, tg = lane & 3;
    const int q0 = warp * 16;

    const int qt = blockIdx.x, h = blockIdx.y, b = blockIdx.z;
    const size_t headOff = ((size_t)(b * Hc + h)) * Sc * Dc;
    const float* Qg = Qg_ + headOff + (size_t)qt * AQ * Dc;
    const float* Kg = Kg_ + headOff;
    const float* Vg = Vg_ + headOff;

    // Load Q tile (fold softmax scale 1/8 into Q)
    {
        const int r  = tid >> 1;
        const int c0 = (tid & 1) * 32;
        #pragma unroll
        for (int c = 0; c < 8; c++) {
            float4 v = *(const float4*)&Qg[(size_t)r * Dc + c0 + c * 4];
            Qs[r][c0 + c * 4 + 0] = f2tf(v.x * 0.125f);
            Qs[r][c0 + c * 4 + 1] = f2tf(v.y * 0.125f);
            Qs[r][c0 + c * 4 + 2] = f2tf(v.z * 0.125f);
            Qs[r][c0 + c * 4 + 3] = f2tf(v.w * 0.125f);
        }
    }

    float o[8][4];
    float mrow[2], lrow[2];
    #pragma unroll
    for (int nt = 0; nt < 8; nt++)
        #pragma unroll
        for (int i = 0; i < 4; i++) o[nt][i] = 0.f;
    mrow[0] = mrow[1] = -INFINITY;
    lrow[0] = lrow[1] = 0.f;

    for (int kt = 0; kt < Sc / 64; kt++) {
        __syncthreads();   // Q visible (iter 0) / prev iter's Kt,Vs reads done
        // Load K transposed [d][kv] and V [kv][d]
        {
            const int kv = tid >> 2;
            const int d0 = (tid & 3) * 16;
            const float* kp = Kg + (size_t)(kt * 64 + kv) * Dc + d0;
            const float* vp = Vg + (size_t)(kt * 64 + kv) * Dc + d0;
            #pragma unroll
            for (int c = 0; c < 4; c++) {
                float4 v = *(const float4*)&kp[c * 4];
                Kt[d0 + c * 4 + 0][kv] = f2tf(v.x);
                Kt[d0 + c * 4 + 1][kv] = f2tf(v.y);
                Kt[d0 + c * 4 + 2][kv] = f2tf(v.z);
                Kt[d0 + c * 4 + 3][kv] = f2tf(v.w);
            }
            #pragma unroll
            for (int c = 0; c < 4; c++) {
                float4 v = *(const float4*)&vp[c * 4];
                Vs[kv][d0 + c * 4 + 0] = f2tf(v.x);
                Vs[kv][d0 + c * 4 + 1] = f2tf(v.y);
                Vs[kv][d0 + c * 4 + 2] = f2tf(v.z);
                Vs[kv][d0 + c * 4 + 3] = f2tf(v.w);
            }
        }
        __syncthreads();

        // S = Q K^T : warp m16 tile x 8 n8 tiles, 8 k-steps over d
        float s[8][4];
        #pragma unroll
        for (int nt = 0; nt < 8; nt++)
            #pragma unroll
            for (int i = 0; i < 4; i++) s[nt][i] = 0.f;

        #pragma unroll
        for (int ks = 0; ks < 8; ks++) {
            uint32_t af[4];
            af[0] = Qs[q0 + g][ks * 8 + tg];
            af[1] = Qs[q0 + g + 8][ks * 8 + tg];
            af[2] = Qs[q0 + g][ks * 8 + tg + 4];
            af[3] = Qs[q0 + g + 8][ks * 8 + tg + 4];
            #pragma unroll
            for (int nt = 0; nt < 8; nt++) {
                uint32_t bf[2];
                bf[0] = Kt[ks * 8 + tg][nt * 8 + g];
                bf[1] = Kt[ks * 8 + tg + 4][nt * 8 + g];
                mma8(s[nt], af, bf);
            }
        }

        // Online softmax per row (rows g and g+8; row spread over the 4-lane quad)
        #pragma unroll
        for (int half = 0; half < 2; half++) {
            float tmax = -INFINITY;
            #pragma unroll
            for (int nt = 0; nt < 8; nt++) {
                tmax = fmaxf(tmax, s[nt][half * 2 + 0]);
                tmax = fmaxf(tmax, s[nt][half * 2 + 1]);
            }
            tmax = fmaxf(tmax, __shfl_xor_sync(0xffffffffu, tmax, 1));
            tmax = fmaxf(tmax, __shfl_xor_sync(0xffffffffu, tmax, 2));
            const float mn   = fmaxf(mrow[half], tmax);
            const float corr = __expf(mrow[half] - mn);
            float rs = 0.f;
            #pragma unroll
            for (int nt = 0; nt < 8; nt++) {
                float p0 = __expf(s[nt][half * 2 + 0] - mn);
                float p1 = __expf(s[nt][half * 2 + 1] - mn);
                rs += p0 + p1;
                Ps[q0 + g + half * 8][nt * 8 + 2 * tg]     = f2tf(p0);
                Ps[q0 + g + half * 8][nt * 8 + 2 * tg + 1] = f2tf(p1);
                o[nt][half * 2 + 0] *= corr;
                o[nt][half * 2 + 1] *= corr;
            }
            rs += __shfl_xor_sync(0xffffffffu, rs, 1);
            rs += __shfl_xor_sync(0xffffffffu, rs, 2);
            lrow[half] = lrow[half] * corr + rs;
            mrow[half] = mn;
        }
        __syncwarp();   // Ps rows are warp-private; fence smem within warp

        // O += P @ V : 8 k-steps over kv, 8 n8 tiles over d
        #pragma unroll
        for (int ks = 0; ks < 8; ks++) {
            uint32_t af[4];
            af[0] = Ps[q0 + g][ks * 8 + tg];
            af[1] = Ps[q0 + g + 8][ks * 8 + tg];
            af[2] = Ps[q0 + g][ks * 8 + tg + 4];
            af[3] = Ps[q0 + g + 8][ks * 8 + tg + 4];
            #pragma unroll
            for (int nt = 0; nt < 8; nt++) {
                uint32_t bf[2];
                bf[0] = Vs[ks * 8 + tg][nt * 8 + g];
                bf[1] = Vs[ks * 8 + tg + 4][nt * 8 + g];
                mma8(o[nt], af, bf);
            }
        }
    }

    // Epilogue: normalize, write concat layout [B,S,E]
    #pragma unroll
    for (int half = 0; half < 2; half++) {
        const float inv = 1.f / lrow[half];
        const int q = qt * AQ + q0 + g + half * 8;
        #pragma unroll
        for (int nt = 0; nt < 8; nt++) {
            const int d = nt * 8 + 2 * tg;
            *(float2*)&Ag_[((size_t)b * Sc + q) * Ec + h * Dc + d] =
                make_float2(o[nt][half * 2 + 0] * inv, o[nt][half * 2 + 1] * inv);
        }
    }
}

// ---------------------------------------------------------------------------
extern "C" void kernel_launch(void* const* d_in, const int* in_sizes, int n_in,
                              void* d_out, int out_size)
{
    const float* x  = (const float*)d_in[0];
    const float* Wq = (const float*)d_in[1];
    const float* bq = (const float*)d_in[2];
    const float* Wk = (const float*)d_in[3];
    const float* bk = (const float*)d_in[4];
    const float* Wv = (const float*)d_in[5];
    const float* bv = (const float*)d_in[6];
    const float* Wo = (const float*)d_in[7];
    const float* bo = (const float*)d_in[8];
    float* out = (float*)d_out;

    float *pQ, *pK, *pV, *pA;
    cudaGetSymbolAddress((void**)&pQ, g_Q);
    cudaGetSymbolAddress((void**)&pK, g_K);
    cudaGetSymbolAddress((void**)&pV, g_V);
    cudaGetSymbolAddress((void**)&pA, g_A);

    const int attnSmem = 384 * QSTR * 4;   // 104448 B
    cudaFuncSetAttribute(attn_tc, cudaFuncAttributeMaxDynamicSharedMemorySize, attnSmem);

    dim3 gg(Ec / GBN, Mtot / GBM);   // (8, 64)
    gemm_tc<<<gg, 256>>>(x, Wq, bq, pQ, 1);
    gemm_tc<<<gg, 256>>>(x, Wk, bk, pK, 1);
    gemm_tc<<<gg, 256>>>(x, Wv, bv, pV, 1);
    attn_tc<<<dim3(Sc / AQ, Hc, Bc), 256, attnSmem>>>(pQ, pK, pV, pA);
    gemm_tc<<<gg, 256>>>(pA, Wo, bo, out, 0);
}

// round 4
// speedup vs baseline: 2.2729x; 1.0008x over previous
#include <cuda_runtime.h>
#include <math.h>
#include <stdint.h>

#define Bc 4
#define Sc 2048
#define Ec 1024
#define Hc 16
#define Dc 64
#define Mtot (Bc*Sc)   // 8192

// Scratch (static device globals: allocation-free)
__device__ float g_Q[(size_t)Bc*Hc*Sc*Dc];
__device__ float g_K[(size_t)Bc*Hc*Sc*Dc];
__device__ float g_V[(size_t)Bc*Hc*Sc*Dc];
__device__ float g_A[(size_t)Bc*Sc*Ec];

// ---- tf32 helpers ---------------------------------------------------------
__device__ __forceinline__ uint32_t f2tf(float x) {
    uint32_t u;
    asm("cvt.rna.tf32.f32 %0, %1;" : "=r"(u) : "f"(x));
    return u;
}

// D += A@B, m16n8k8 tf32, in-place accumulate
__device__ __forceinline__ void mma8(float* d, const uint32_t* a, const uint32_t* b) {
    asm volatile(
        "mma.sync.aligned.m16n8k8.row.col.f32.tf32.tf32.f32 "
        "{%0,%1,%2,%3}, {%4,%5,%6,%7}, {%8,%9}, {%0,%1,%2,%3};"
        : "+f"(d[0]), "+f"(d[1]), "+f"(d[2]), "+f"(d[3])
        : "r"(a[0]), "r"(a[1]), "r"(a[2]), "r"(a[3]), "r"(b[0]), "r"(b[1]));
}

// ---------------- GEMM: C[M,1024] = A[M,1024] @ W[1024,1024] + bias --------
// 128x128 tile, BK=32, 256 threads (8 warps), warp tile 64x32.
#define GBM 128
#define GBN 128
#define GBK 32
#define ASTR 36
#define WSTR 132

__global__ __launch_bounds__(256, 2) void gemm_tc(
    const float* __restrict__ A, const float* __restrict__ W,
    const float* __restrict__ bias, float* __restrict__ C, int split)
{
    __shared__ uint32_t As[GBM][ASTR];   // [m][k]
    __shared__ uint32_t Ws[GBK][WSTR];   // [k][n]

    const int tid  = threadIdx.x;
    const int lane = tid & 31, warp = tid >> 5;
    const int g = lane >> 2, tg = lane & 3;
    const int wm = warp >> 2, wn = warp & 3;          // 2 x 4 warp grid
    const int bm = blockIdx.y * GBM, bn = blockIdx.x * GBN;

    float acc[4][4][4];
    #pragma unroll
    for (int mt = 0; mt < 4; mt++)
        #pragma unroll
        for (int nt = 0; nt < 4; nt++)
            #pragma unroll
            for (int i = 0; i < 4; i++) acc[mt][nt][i] = 0.f;

    const int arow  = tid >> 1;          // 0..127
    const int acol0 = (tid & 1) * 16;    // 0 / 16
    const int wrow  = tid >> 3;          // 0..31
    const int wcol0 = (tid & 7) * 16;    // 0..112

    for (int k0 = 0; k0 < Ec; k0 += GBK) {
        #pragma unroll
        for (int c = 0; c < 4; c++) {
            float4 v = *(const float4*)&A[(size_t)(bm + arow) * Ec + k0 + acol0 + c * 4];
            As[arow][acol0 + c * 4 + 0] = f2tf(v.x);
            As[arow][acol0 + c * 4 + 1] = f2tf(v.y);
            As[arow][acol0 + c * 4 + 2] = f2tf(v.z);
            As[arow][acol0 + c * 4 + 3] = f2tf(v.w);
        }
        #pragma unroll
        for (int c = 0; c < 4; c++) {
            float4 v = *(const float4*)&W[(size_t)(k0 + wrow) * Ec + bn + wcol0 + c * 4];
            Ws[wrow][wcol0 + c * 4 + 0] = f2tf(v.x);
            Ws[wrow][wcol0 + c * 4 + 1] = f2tf(v.y);
            Ws[wrow][wcol0 + c * 4 + 2] = f2tf(v.z);
            Ws[wrow][wcol0 + c * 4 + 3] = f2tf(v.w);
        }
        __syncthreads();

        #pragma unroll
        for (int ks = 0; ks < 4; ks++) {
            uint32_t af[4][4], bf[4][2];
            #pragma unroll
            for (int mt = 0; mt < 4; mt++) {
                const int r = wm * 64 + mt * 16 + g;
                af[mt][0] = As[r][ks * 8 + tg];
                af[mt][1] = As[r + 8][ks * 8 + tg];
                af[mt][2] = As[r][ks * 8 + tg + 4];
                af[mt][3] = As[r + 8][ks * 8 + tg + 4];
            }
            #pragma unroll
            for (int nt = 0; nt < 4; nt++) {
                const int cb = wn * 32 + nt * 8 + g;
                bf[nt][0] = Ws[ks * 8 + tg][cb];
                bf[nt][1] = Ws[ks * 8 + tg + 4][cb];
            }
            #pragma unroll
            for (int mt = 0; mt < 4; mt++)
                #pragma unroll
                for (int nt = 0; nt < 4; nt++)
                    mma8(acc[mt][nt], af[mt], bf[nt]);
        }
        __syncthreads();
    }

    #pragma unroll
    for (int mt = 0; mt < 4; mt++) {
        #pragma unroll
        for (int half = 0; half < 2; half++) {
            const int m = bm + wm * 64 + mt * 16 + g + half * 8;
            #pragma unroll
            for (int nt = 0; nt < 4; nt++) {
                const int n = bn + wn * 32 + nt * 8 + 2 * tg;
                float v0 = acc[mt][nt][half * 2 + 0] + bias[n];
                float v1 = acc[mt][nt][half * 2 + 1] + bias[n + 1];
                if (split) {
                    const int b = m >> 11, s = m & 2047;
                    const int h = n >> 6, d = n & 63;
                    *(float2*)&C[(((size_t)(b * Hc + h)) * Sc + s) * Dc + d] =
                        make_float2(v0, v1);
                } else {
                    *(float2*)&C[(size_t)m * Ec + n] = make_float2(v0, v1);
                }
            }
        }
    }
}

// ---------------- Flash attention (tf32 mma): 128 q / CTA, 8 warps ---------
#define AQ 128
#define QSTR 68

__global__ __launch_bounds__(256, 2) void attn_tc(
    const float* __restrict__ Qg_, const float* __restrict__ Kg_,
    const float* __restrict__ Vg_, float* __restrict__ Ag_)
{
    extern __shared__ uint32_t sm[];
    uint32_t (*Qs)[QSTR] = (uint32_t(*)[QSTR])(sm);                 // [128][68]
    uint32_t (*Kt)[QSTR] = (uint32_t(*)[QSTR])(sm + 128 * QSTR);    // [d][kv]
    uint32_t (*Vs)[QSTR] = (uint32_t(*)[QSTR])(sm + 192 * QSTR);    // [kv][d]
    uint32_t (*Ps)[QSTR] = (uint32_t(*)[QSTR])(sm + 256 * QSTR);    // [q][kv]

    const int tid  = threadIdx.x;
    const int lane = tid & 31, warp = tid >> 5;
    const int g = lane >> 2, tg = lane & 3;
    const int q0 = warp * 16;

    const int qt = blockIdx.x, h = blockIdx.y, b = blockIdx.z;
    const size_t headOff = ((size_t)(b * Hc + h)) * Sc * Dc;
    const float* Qg = Qg_ + headOff + (size_t)qt * AQ * Dc;
    const float* Kg = Kg_ + headOff;
    const float* Vg = Vg_ + headOff;

    // Load Q tile (fold softmax scale 1/8 into Q)
    {
        const int r  = tid >> 1;
        const int c0 = (tid & 1) * 32;
        #pragma unroll
        for (int c = 0; c < 8; c++) {
            float4 v = *(const float4*)&Qg[(size_t)r * Dc + c0 + c * 4];
            Qs[r][c0 + c * 4 + 0] = f2tf(v.x * 0.125f);
            Qs[r][c0 + c * 4 + 1] = f2tf(v.y * 0.125f);
            Qs[r][c0 + c * 4 + 2] = f2tf(v.z * 0.125f);
            Qs[r][c0 + c * 4 + 3] = f2tf(v.w * 0.125f);
        }
    }

    float o[8][4];
    float mrow[2], lrow[2];
    #pragma unroll
    for (int nt = 0; nt < 8; nt++)
        #pragma unroll
        for (int i = 0; i < 4; i++) o[nt][i] = 0.f;
    mrow[0] = mrow[1] = -INFINITY;
    lrow[0] = lrow[1] = 0.f;

    for (int kt = 0; kt < Sc / 64; kt++) {
        __syncthreads();   // Q visible (iter 0) / prev iter's Kt,Vs reads done
        // Load K transposed [d][kv] and V [kv][d]
        {
            const int kv = tid >> 2;
            const int d0 = (tid & 3) * 16;
            const float* kp = Kg + (size_t)(kt * 64 + kv) * Dc + d0;
            const float* vp = Vg + (size_t)(kt * 64 + kv) * Dc + d0;
            #pragma unroll
            for (int c = 0; c < 4; c++) {
                float4 v = *(const float4*)&kp[c * 4];
                Kt[d0 + c * 4 + 0][kv] = f2tf(v.x);
                Kt[d0 + c * 4 + 1][kv] = f2tf(v.y);
                Kt[d0 + c * 4 + 2][kv] = f2tf(v.z);
                Kt[d0 + c * 4 + 3][kv] = f2tf(v.w);
            }
            #pragma unroll
            for (int c = 0; c < 4; c++) {
                float4 v = *(const float4*)&vp[c * 4];
                Vs[kv][d0 + c * 4 + 0] = f2tf(v.x);
                Vs[kv][d0 + c * 4 + 1] = f2tf(v.y);
                Vs[kv][d0 + c * 4 + 2] = f2tf(v.z);
                Vs[kv][d0 + c * 4 + 3] = f2tf(v.w);
            }
        }
        __syncthreads();

        // S = Q K^T : warp m16 tile x 8 n8 tiles, 8 k-steps over d
        float s[8][4];
        #pragma unroll
        for (int nt = 0; nt < 8; nt++)
            #pragma unroll
            for (int i = 0; i < 4; i++) s[nt][i] = 0.f;

        #pragma unroll
        for (int ks = 0; ks < 8; ks++) {
            uint32_t af[4];
            af[0] = Qs[q0 + g][ks * 8 + tg];
            af[1] = Qs[q0 + g + 8][ks * 8 + tg];
            af[2] = Qs[q0 + g][ks * 8 + tg + 4];
            af[3] = Qs[q0 + g + 8][ks * 8 + tg + 4];
            #pragma unroll
            for (int nt = 0; nt < 8; nt++) {
                uint32_t bf[2];
                bf[0] = Kt[ks * 8 + tg][nt * 8 + g];
                bf[1] = Kt[ks * 8 + tg + 4][nt * 8 + g];
                mma8(s[nt], af, bf);
            }
        }

        // Online softmax per row (rows g and g+8; row spread over the 4-lane quad)
        #pragma unroll
        for (int half = 0; half < 2; half++) {
            float tmax = -INFINITY;
            #pragma unroll
            for (int nt = 0; nt < 8; nt++) {
                tmax = fmaxf(tmax, s[nt][half * 2 + 0]);
                tmax = fmaxf(tmax, s[nt][half * 2 + 1]);
            }
            tmax = fmaxf(tmax, __shfl_xor_sync(0xffffffffu, tmax, 1));
            tmax = fmaxf(tmax, __shfl_xor_sync(0xffffffffu, tmax, 2));
            const float mn   = fmaxf(mrow[half], tmax);
            const float corr = __expf(mrow[half] - mn);
            float rs = 0.f;
            #pragma unroll
            for (int nt = 0; nt < 8; nt++) {
                float p0 = __expf(s[nt][half * 2 + 0] - mn);
                float p1 = __expf(s[nt][half * 2 + 1] - mn);
                rs += p0 + p1;
                Ps[q0 + g + half * 8][nt * 8 + 2 * tg]     = f2tf(p0);
                Ps[q0 + g + half * 8][nt * 8 + 2 * tg + 1] = f2tf(p1);
                o[nt][half * 2 + 0] *= corr;
                o[nt][half * 2 + 1] *= corr;
            }
            rs += __shfl_xor_sync(0xffffffffu, rs, 1);
            rs += __shfl_xor_sync(0xffffffffu, rs, 2);
            lrow[half] = lrow[half] * corr + rs;
            mrow[half] = mn;
        }
        __syncwarp();   // Ps rows are warp-private; fence smem within warp

        // O += P @ V : 8 k-steps over kv, 8 n8 tiles over d
        #pragma unroll
        for (int ks = 0; ks < 8; ks++) {
            uint32_t af[4];
            af[0] = Ps[q0 + g][ks * 8 + tg];
            af[1] = Ps[q0 + g + 8][ks * 8 + tg];
            af[2] = Ps[q0 + g][ks * 8 + tg + 4];
            af[3] = Ps[q0 + g + 8][ks * 8 + tg + 4];
            #pragma unroll
            for (int nt = 0; nt < 8; nt++) {
                uint32_t bf[2];
                bf[0] = Vs[ks * 8 + tg][nt * 8 + g];
                bf[1] = Vs[ks * 8 + tg + 4][nt * 8 + g];
                mma8(o[nt], af, bf);
            }
        }
    }

    // Epilogue: normalize, write concat layout [B,S,E]
    #pragma unroll
    for (int half = 0; half < 2; half++) {
        const float inv = 1.f / lrow[half];
        const int q = qt * AQ + q0 + g + half * 8;
        #pragma unroll
        for (int nt = 0; nt < 8; nt++) {
            const int d = nt * 8 + 2 * tg;
            *(float2*)&Ag_[((size_t)b * Sc + q) * Ec + h * Dc + d] =
                make_float2(o[nt][half * 2 + 0] * inv, o[nt][half * 2 + 1] * inv);
        }
    }
}

// ---------------------------------------------------------------------------
extern "C" void kernel_launch(void* const* d_in, const int* in_sizes, int n_in,
                              void* d_out, int out_size)
{
    const float* x  = (const float*)d_in[0];
    const float* Wq = (const float*)d_in[1];
    const float* bq = (const float*)d_in[2];
    const float* Wk = (const float*)d_in[3];
    const float* bk = (const float*)d_in[4];
    const float* Wv = (const float*)d_in[5];
    const float* bv = (const float*)d_in[6];
    const float* Wo = (const float*)d_in[7];
    const float* bo = (const float*)d_in[8];
    float* out = (float*)d_out;

    float *pQ, *pK, *pV, *pA;
    cudaGetSymbolAddress((void**)&pQ, g_Q);
    cudaGetSymbolAddress((void**)&pK, g_K);
    cudaGetSymbolAddress((void**)&pV, g_V);
    cudaGetSymbolAddress((void**)&pA, g_A);

    const int attnSmem = 384 * QSTR * 4;   // 104448 B
    cudaFuncSetAttribute(attn_tc, cudaFuncAttributeMaxDynamicSharedMemorySize, attnSmem);

    dim3 gg(Ec / GBN, Mtot / GBM);   // (8, 64)
    gemm_tc<<<gg, 256>>>(x, Wq, bq, pQ, 1);
    gemm_tc<<<gg, 256>>>(x, Wk, bk, pK, 1);
    gemm_tc<<<gg, 256>>>(x, Wv, bv, pV, 1);
    attn_tc<<<dim3(Sc / AQ, Hc, Bc), 256, attnSmem>>>(pQ, pK, pV, pA);
    gemm_tc<<<gg, 256>>>(pA, Wo, bo, out, 0);
}

// round 5
// speedup vs baseline: 2.7884x; 1.2268x over previous
#include <cuda_runtime.h>
#include <math.h>
#include <stdint.h>

#define Bc 4
#define Sc 2048
#define Ec 1024
#define Hc 16
#define Dc 64
#define Mtot (Bc*Sc)   // 8192

// Scratch (static device globals: allocation-free)
__device__ float g_Q[(size_t)Bc*Hc*Sc*Dc];
__device__ float g_K[(size_t)Bc*Hc*Sc*Dc];
__device__ float g_V[(size_t)Bc*Hc*Sc*Dc];
__device__ float g_A[(size_t)Bc*Sc*Ec];

// ---- tf32 helpers ---------------------------------------------------------
__device__ __forceinline__ uint32_t f2tf(float x) {
    uint32_t u;
    asm("cvt.rna.tf32.f32 %0, %1;" : "=r"(u) : "f"(x));
    return u;
}

// D += A@B, m16n8k8 tf32, in-place accumulate
__device__ __forceinline__ void mma8(float* d, const uint32_t* a, const uint32_t* b) {
    asm volatile(
        "mma.sync.aligned.m16n8k8.row.col.f32.tf32.tf32.f32 "
        "{%0,%1,%2,%3}, {%4,%5,%6,%7}, {%8,%9}, {%0,%1,%2,%3};"
        : "+f"(d[0]), "+f"(d[1]), "+f"(d[2]), "+f"(d[3])
        : "r"(a[0]), "r"(a[1]), "r"(a[2]), "r"(a[3]), "r"(b[0]), "r"(b[1]));
}

// ---------------- GEMM: C[M,1024] = A[M,1024] @ W[1024,1024] + bias --------
// (unchanged from R3 — proven)
#define GBM 128
#define GBN 128
#define GBK 32
#define ASTR 36
#define WSTR 132

__global__ __launch_bounds__(256, 2) void gemm_tc(
    const float* __restrict__ A, const float* __restrict__ W,
    const float* __restrict__ bias, float* __restrict__ C, int split)
{
    __shared__ uint32_t As[GBM][ASTR];   // [m][k]
    __shared__ uint32_t Ws[GBK][WSTR];   // [k][n]

    const int tid  = threadIdx.x;
    const int lane = tid & 31, warp = tid >> 5;
    const int g = lane >> 2, tg = lane & 3;
    const int wm = warp >> 2, wn = warp & 3;          // 2 x 4 warp grid
    const int bm = blockIdx.y * GBM, bn = blockIdx.x * GBN;

    float acc[4][4][4];
    #pragma unroll
    for (int mt = 0; mt < 4; mt++)
        #pragma unroll
        for (int nt = 0; nt < 4; nt++)
            #pragma unroll
            for (int i = 0; i < 4; i++) acc[mt][nt][i] = 0.f;

    const int arow  = tid >> 1;          // 0..127
    const int acol0 = (tid & 1) * 16;    // 0 / 16
    const int wrow  = tid >> 3;          // 0..31
    const int wcol0 = (tid & 7) * 16;    // 0..112

    for (int k0 = 0; k0 < Ec; k0 += GBK) {
        #pragma unroll
        for (int c = 0; c < 4; c++) {
            float4 v = *(const float4*)&A[(size_t)(bm + arow) * Ec + k0 + acol0 + c * 4];
            As[arow][acol0 + c * 4 + 0] = f2tf(v.x);
            As[arow][acol0 + c * 4 + 1] = f2tf(v.y);
            As[arow][acol0 + c * 4 + 2] = f2tf(v.z);
            As[arow][acol0 + c * 4 + 3] = f2tf(v.w);
        }
        #pragma unroll
        for (int c = 0; c < 4; c++) {
            float4 v = *(const float4*)&W[(size_t)(k0 + wrow) * Ec + bn + wcol0 + c * 4];
            Ws[wrow][wcol0 + c * 4 + 0] = f2tf(v.x);
            Ws[wrow][wcol0 + c * 4 + 1] = f2tf(v.y);
            Ws[wrow][wcol0 + c * 4 + 2] = f2tf(v.z);
            Ws[wrow][wcol0 + c * 4 + 3] = f2tf(v.w);
        }
        __syncthreads();

        #pragma unroll
        for (int ks = 0; ks < 4; ks++) {
            uint32_t af[4][4], bf[4][2];
            #pragma unroll
            for (int mt = 0; mt < 4; mt++) {
                const int r = wm * 64 + mt * 16 + g;
                af[mt][0] = As[r][ks * 8 + tg];
                af[mt][1] = As[r + 8][ks * 8 + tg];
                af[mt][2] = As[r][ks * 8 + tg + 4];
                af[mt][3] = As[r + 8][ks * 8 + tg + 4];
            }
            #pragma unroll
            for (int nt = 0; nt < 4; nt++) {
                const int cb = wn * 32 + nt * 8 + g;
                bf[nt][0] = Ws[ks * 8 + tg][cb];
                bf[nt][1] = Ws[ks * 8 + tg + 4][cb];
            }
            #pragma unroll
            for (int mt = 0; mt < 4; mt++)
                #pragma unroll
                for (int nt = 0; nt < 4; nt++)
                    mma8(acc[mt][nt], af[mt], bf[nt]);
        }
        __syncthreads();
    }

    #pragma unroll
    for (int mt = 0; mt < 4; mt++) {
        #pragma unroll
        for (int half = 0; half < 2; half++) {
            const int m = bm + wm * 64 + mt * 16 + g + half * 8;
            #pragma unroll
            for (int nt = 0; nt < 4; nt++) {
                const int n = bn + wn * 32 + nt * 8 + 2 * tg;
                float v0 = acc[mt][nt][half * 2 + 0] + bias[n];
                float v1 = acc[mt][nt][half * 2 + 1] + bias[n + 1];
                if (split) {
                    const int b = m >> 11, s = m & 2047;
                    const int h = n >> 6, d = n & 63;
                    *(float2*)&C[(((size_t)(b * Hc + h)) * Sc + s) * Dc + d] =
                        make_float2(v0, v1);
                } else {
                    *(float2*)&C[(size_t)m * Ec + n] = make_float2(v0, v1);
                }
            }
        }
    }
}

// ---------------- Flash attention (tf32 mma, P in registers) ---------------
// 128 q / CTA, 8 warps, warp m16 tile x full kv=64.
// Kt: [d][kv] stride 72, col swizzle kv ^ 8*((d>>4)&3)        -> CF stores+loads
// Vs: [kv][d] stride 72, col swizzle d ^ 8*(((kv>>4)^(kv>>2))&3) -> CF loads
// S-MMA feeds K row 8nt + pi(g), pi(n)=(n>>1)+4(n&1): accumulator layout
// becomes the PV A-fragment layout => P never touches smem.
#define AQ 128
#define QSTR 68
#define KSTR 72

__global__ __launch_bounds__(256, 2) void attn_tc(
    const float* __restrict__ Qg_, const float* __restrict__ Kg_,
    const float* __restrict__ Vg_, float* __restrict__ Ag_)
{
    extern __shared__ uint32_t sm[];
    uint32_t (*Qs)[QSTR] = (uint32_t(*)[QSTR])(sm);            // [128][68]
    uint32_t (*Kt)[KSTR] = (uint32_t(*)[KSTR])(sm + 8704);     // [64 d][72]
    uint32_t (*Vs)[KSTR] = (uint32_t(*)[KSTR])(sm + 13312);    // [64 kv][72]

    const int tid  = threadIdx.x;
    const int lane = tid & 31, warp = tid >> 5;
    const int g = lane >> 2, tg = lane & 3;
    const int q0 = warp * 16;
    const int pig = (g >> 1) + 4 * (g & 1);    // pi permutation of g

    const int qt = blockIdx.x, h = blockIdx.y, b = blockIdx.z;
    const size_t headOff = ((size_t)(b * Hc + h)) * Sc * Dc;
    const float* Qg = Qg_ + headOff + (size_t)qt * AQ * Dc;
    const float* Kg = Kg_ + headOff;
    const float* Vg = Vg_ + headOff;

    // Load Q tile (fold softmax scale 1/8 into Q); once per CTA
    {
        const int r  = tid >> 1;
        const int c0 = (tid & 1) * 32;
        #pragma unroll
        for (int c = 0; c < 8; c++) {
            float4 v = *(const float4*)&Qg[(size_t)r * Dc + c0 + c * 4];
            Qs[r][c0 + c * 4 + 0] = f2tf(v.x * 0.125f);
            Qs[r][c0 + c * 4 + 1] = f2tf(v.y * 0.125f);
            Qs[r][c0 + c * 4 + 2] = f2tf(v.z * 0.125f);
            Qs[r][c0 + c * 4 + 3] = f2tf(v.w * 0.125f);
        }
    }

    float o[8][4];
    float mrow[2], lrow[2];
    #pragma unroll
    for (int nt = 0; nt < 8; nt++)
        #pragma unroll
        for (int i = 0; i < 4; i++) o[nt][i] = 0.f;
    mrow[0] = mrow[1] = -INFINITY;
    lrow[0] = lrow[1] = 0.f;

    const int kv  = tid >> 2;           // 0..63
    const int d0  = (tid & 3) * 16;     // 0,16,32,48
    const int swK = 8 * ((d0 >> 4) & 3);                       // K store col xor
    const int swV = 8 * (((kv >> 4) ^ (kv >> 2)) & 3);         // V store col xor

    for (int kt = 0; kt < Sc / 64; kt++) {
        __syncthreads();   // smem free (Q store visible on iter 0)
        {
            const float* kp = Kg + (size_t)(kt * 64 + kv) * Dc + d0;
            const float* vp = Vg + (size_t)(kt * 64 + kv) * Dc + d0;
            const int kvp = kv ^ swK;
            #pragma unroll
            for (int c = 0; c < 4; c++) {
                float4 k4 = *(const float4*)&kp[c * 4];
                Kt[d0 + c * 4 + 0][kvp] = f2tf(k4.x);
                Kt[d0 + c * 4 + 1][kvp] = f2tf(k4.y);
                Kt[d0 + c * 4 + 2][kvp] = f2tf(k4.z);
                Kt[d0 + c * 4 + 3][kvp] = f2tf(k4.w);
                float4 v4 = *(const float4*)&vp[c * 4];
                uint32_t* dst = &Vs[kv][(d0 + c * 4) ^ swV];
                *(uint4*)dst = make_uint4(f2tf(v4.x), f2tf(v4.y),
                                          f2tf(v4.z), f2tf(v4.w));
            }
        }
        __syncthreads();

        // S = Q K^T, B columns permuted by pi
        float s[8][4];
        #pragma unroll
        for (int nt = 0; nt < 8; nt++)
            #pragma unroll
            for (int i = 0; i < 4; i++) s[nt][i] = 0.f;

        #pragma unroll
        for (int ks = 0; ks < 8; ks++) {
            uint32_t af[4];
            af[0] = Qs[q0 + g][ks * 8 + tg];
            af[1] = Qs[q0 + g + 8][ks * 8 + tg];
            af[2] = Qs[q0 + g][ks * 8 + tg + 4];
            af[3] = Qs[q0 + g + 8][ks * 8 + tg + 4];
            const int r0 = ks * 8 + tg;            // rows r0, r0+4 share >>4
            const int sw = 8 * ((r0 >> 4) & 3);
            #pragma unroll
            for (int nt = 0; nt < 8; nt++) {
                const int col = (8 * nt + pig) ^ sw;
                uint32_t bf[2];
                bf[0] = Kt[r0][col];
                bf[1] = Kt[r0 + 4][col];
                mma8(s[nt], af, bf);
            }
        }
        // thread holds S(q0+g+8h, kv=8nt+tg)   in s[nt][2h]
        //              S(q0+g+8h, kv=8nt+tg+4) in s[nt][2h+1]

        // Online softmax (rows spread over the 4-lane quad; pi-invariant)
        #pragma unroll
        for (int half = 0; half < 2; half++) {
            float tmax = -INFINITY;
            #pragma unroll
            for (int nt = 0; nt < 8; nt++) {
                tmax = fmaxf(tmax, s[nt][half * 2 + 0]);
                tmax = fmaxf(tmax, s[nt][half * 2 + 1]);
            }
            tmax = fmaxf(tmax, __shfl_xor_sync(0xffffffffu, tmax, 1));
            tmax = fmaxf(tmax, __shfl_xor_sync(0xffffffffu, tmax, 2));
            const float mn   = fmaxf(mrow[half], tmax);
            const float corr = __expf(mrow[half] - mn);
            float rs = 0.f;
            #pragma unroll
            for (int nt = 0; nt < 8; nt++) {
                float p0 = __expf(s[nt][half * 2 + 0] - mn);
                float p1 = __expf(s[nt][half * 2 + 1] - mn);
                s[nt][half * 2 + 0] = p0;
                s[nt][half * 2 + 1] = p1;
                rs += p0 + p1;
                o[nt][half * 2 + 0] *= corr;
                o[nt][half * 2 + 1] *= corr;
            }
            rs += __shfl_xor_sync(0xffffffffu, rs, 1);
            rs += __shfl_xor_sync(0xffffffffu, rs, 2);
            lrow[half] = lrow[half] * corr + rs;
            mrow[half] = mn;
        }

        // O += P @ V : P fragments straight from the S accumulator
        #pragma unroll
        for (int ks = 0; ks < 8; ks++) {
            uint32_t af[4];
            af[0] = f2tf(s[ks][0]);   // (row g,   kv 8ks+tg)
            af[1] = f2tf(s[ks][2]);   // (row g+8, kv 8ks+tg)
            af[2] = f2tf(s[ks][1]);   // (row g,   kv 8ks+tg+4)
            af[3] = f2tf(s[ks][3]);   // (row g+8, kv 8ks+tg+4)
            const int r0 = 8 * ks + tg;
            const int s0 = ((ks >> 1) ^ (2 * ks)) & 3;   // swz(row r0)
            const int s1 = s0 ^ 1;                       // swz(row r0+4)
            #pragma unroll
            for (int nt = 0; nt < 8; nt++) {
                uint32_t bf[2];
                bf[0] = Vs[r0][(8 * nt + g) ^ (8 * s0)];
                bf[1] = Vs[r0 + 4][(8 * nt + g) ^ (8 * s1)];
                mma8(o[nt], af, bf);
            }
        }
    }

    // Epilogue: normalize, write concat layout [B,S,E]
    #pragma unroll
    for (int half = 0; half < 2; half++) {
        const float inv = 1.f / lrow[half];
        const int q = qt * AQ + q0 + g + half * 8;
        #pragma unroll
        for (int nt = 0; nt < 8; nt++) {
            const int d = nt * 8 + 2 * tg;
            *(float2*)&Ag_[((size_t)b * Sc + q) * Ec + h * Dc + d] =
                make_float2(o[nt][half * 2 + 0] * inv, o[nt][half * 2 + 1] * inv);
        }
    }
}

// ---------------------------------------------------------------------------
extern "C" void kernel_launch(void* const* d_in, const int* in_sizes, int n_in,
                              void* d_out, int out_size)
{
    const float* x  = (const float*)d_in[0];
    const float* Wq = (const float*)d_in[1];
    const float* bq = (const float*)d_in[2];
    const float* Wk = (const float*)d_in[3];
    const float* bk = (const float*)d_in[4];
    const float* Wv = (const float*)d_in[5];
    const float* bv = (const float*)d_in[6];
    const float* Wo = (const float*)d_in[7];
    const float* bo = (const float*)d_in[8];
    float* out = (float*)d_out;

    float *pQ, *pK, *pV, *pA;
    cudaGetSymbolAddress((void**)&pQ, g_Q);
    cudaGetSymbolAddress((void**)&pK, g_K);
    cudaGetSymbolAddress((void**)&pV, g_V);
    cudaGetSymbolAddress((void**)&pA, g_A);

    const int attnSmem = (128 * QSTR + 2 * 64 * KSTR) * 4;   // 71680 B
    cudaFuncSetAttribute(attn_tc, cudaFuncAttributeMaxDynamicSharedMemorySize, attnSmem);

    dim3 gg(Ec / GBN, Mtot / GBM);   // (8, 64)
    gemm_tc<<<gg, 256>>>(x, Wq, bq, pQ, 1);
    gemm_tc<<<gg, 256>>>(x, Wk, bk, pK, 1);
    gemm_tc<<<gg, 256>>>(x, Wv, bv, pV, 1);
    attn_tc<<<dim3(Sc / AQ, Hc, Bc), 256, attnSmem>>>(pQ, pK, pV, pA);
    gemm_tc<<<gg, 256>>>(pA, Wo, bo, out, 0);
}

// round 8
// speedup vs baseline: 3.0948x; 1.1099x over previous
#include <cuda_runtime.h>
#include <math.h>
#include <stdint.h>

#define Bc 4
#define Sc 2048
#define Ec 1024
#define Hc 16
#define Dc 64
#define Mtot (Bc*Sc)   // 8192

// Scratch (static device globals: allocation-free)
__device__ float g_Q[(size_t)Bc*Hc*Sc*Dc];
__device__ float g_K[(size_t)Bc*Hc*Sc*Dc];
__device__ float g_V[(size_t)Bc*Hc*Sc*Dc];
__device__ float g_A[(size_t)Bc*Sc*Ec];

// ---- helpers --------------------------------------------------------------
__device__ __forceinline__ uint32_t f2tf(float x) {
    uint32_t u;
    asm("cvt.rna.tf32.f32 %0, %1;" : "=r"(u) : "f"(x));
    return u;
}

__device__ __forceinline__ void mma8(float* d, const uint32_t* a, const uint32_t* b) {
    asm volatile(
        "mma.sync.aligned.m16n8k8.row.col.f32.tf32.tf32.f32 "
        "{%0,%1,%2,%3}, {%4,%5,%6,%7}, {%8,%9}, {%0,%1,%2,%3};"
        : "+f"(d[0]), "+f"(d[1]), "+f"(d[2]), "+f"(d[3])
        : "r"(a[0]), "r"(a[1]), "r"(a[2]), "r"(a[3]), "r"(b[0]), "r"(b[1]));
}

__device__ __forceinline__ void cpa16(uint32_t dst, const void* src) {
    asm volatile("cp.async.cg.shared.global [%0], [%1], 16;" :: "r"(dst), "l"(src));
}
__device__ __forceinline__ void cp_commit() {
    asm volatile("cp.async.commit_group;" ::: "memory");
}
__device__ __forceinline__ void cp_wait1() {
    asm volatile("cp.async.wait_group 1;" ::: "memory");
}
__device__ __forceinline__ void cp_wait0() {
    asm volatile("cp.async.wait_group 0;" ::: "memory");
}

// ---------------- GEMM: C[M,1024] = A[M,1024] @ W[1024,1024] + bias --------
// 128x128 tile, BK=32, 256 threads (8 warps), warp tile 64x32.
// Raw f32 tiles via cp.async double buffer; cvt to tf32 at frag load.
// As stride 36 (bank 4g+tg CF), Ws stride 136 (bank 8tg+g CF).
#define GBM 128
#define GBN 128
#define GBK 32
#define ASTR 36
#define WSTR 136
#define ASTG (GBM*ASTR)       // 4608 words / stage
#define WSTG (GBK*WSTR)       // 4352 words / stage
#define GSM  (2*(ASTG+WSTG))  // 17920 words = 71680 B

__global__ __launch_bounds__(256, 2) void gemm_tc(
    const float* __restrict__ A, const float* __restrict__ W,
    const float* __restrict__ bias, float* __restrict__ C, int split)
{
    extern __shared__ float smf[];
    float* Asb = smf;                 // 2 stages [128][36]
    float* Wsb = smf + 2 * ASTG;      // 2 stages [32][136]

    const int tid  = threadIdx.x;
    const int lane = tid & 31, warp = tid >> 5;
    const int g = lane >> 2, tg = lane & 3;
    const int wm = warp >> 2, wn = warp & 3;
    const int bm = blockIdx.y * GBM, bn = blockIdx.x * GBN;

    // copy mappings
    const int ar = tid >> 1;                 // A row 0..127
    const int ac = (tid & 1) * 16;           // A col word base (+4j)
    const int wr = tid >> 3;                 // W row 0..31
    const int wc = (tid & 7) * 16;           // W col word base (+4j)
    const float* Ab = A + (size_t)(bm + ar) * Ec + ac;
    const float* Wb = W + (size_t)wr * Ec + bn + wc;

    const uint32_t asA = (uint32_t)__cvta_generic_to_shared(Asb) + (ar * ASTR + ac) * 4;
    const uint32_t asW = (uint32_t)__cvta_generic_to_shared(Wsb) + (wr * WSTR + wc) * 4;

    float acc[4][4][4];
    #pragma unroll
    for (int mt = 0; mt < 4; mt++)
        #pragma unroll
        for (int nt = 0; nt < 4; nt++)
            #pragma unroll
            for (int i = 0; i < 4; i++) acc[mt][nt][i] = 0.f;

    // prologue: stage 0
    #pragma unroll
    for (int j = 0; j < 4; j++) cpa16(asA + 16 * j, Ab + 4 * j);
    #pragma unroll
    for (int j = 0; j < 4; j++) cpa16(asW + 16 * j, Wb + 4 * j);
    cp_commit();

    const int NIT = Ec / GBK;   // 32
    for (int it = 0; it < NIT; it++) {
        const int p = it & 1;
        if (it + 1 < NIT) {
            const int k0 = (it + 1) * GBK;
            const uint32_t dA = asA + (1 - p) * ASTG * 4;
            const uint32_t dW = asW + (1 - p) * WSTG * 4;
            #pragma unroll
            for (int j = 0; j < 4; j++) cpa16(dA + 16 * j, Ab + k0 + 4 * j);
            #pragma unroll
            for (int j = 0; j < 4; j++) cpa16(dW + 16 * j, Wb + (size_t)k0 * Ec + 4 * j);
            cp_commit();
            cp_wait1();
        } else {
            cp_wait0();
        }
        __syncthreads();

        const float* As = Asb + p * ASTG;
        const float* Ws = Wsb + p * WSTG;

        #pragma unroll
        for (int ks = 0; ks < 4; ks++) {
            uint32_t af[4][4], bf[4][2];
            #pragma unroll
            for (int mt = 0; mt < 4; mt++) {
                const int r = wm * 64 + mt * 16 + g;
                af[mt][0] = f2tf(As[r * ASTR + ks * 8 + tg]);
                af[mt][1] = f2tf(As[(r + 8) * ASTR + ks * 8 + tg]);
                af[mt][2] = f2tf(As[r * ASTR + ks * 8 + tg + 4]);
                af[mt][3] = f2tf(As[(r + 8) * ASTR + ks * 8 + tg + 4]);
            }
            #pragma unroll
            for (int nt = 0; nt < 4; nt++) {
                const int cb = wn * 32 + nt * 8 + g;
                bf[nt][0] = f2tf(Ws[(ks * 8 + tg) * WSTR + cb]);
                bf[nt][1] = f2tf(Ws[(ks * 8 + tg + 4) * WSTR + cb]);
            }
            #pragma unroll
            for (int mt = 0; mt < 4; mt++)
                #pragma unroll
                for (int nt = 0; nt < 4; nt++)
                    mma8(acc[mt][nt], af[mt], bf[nt]);
        }
        __syncthreads();
    }

    #pragma unroll
    for (int mt = 0; mt < 4; mt++) {
        #pragma unroll
        for (int half = 0; half < 2; half++) {
            const int m = bm + wm * 64 + mt * 16 + g + half * 8;
            #pragma unroll
            for (int nt = 0; nt < 4; nt++) {
                const int n = bn + wn * 32 + nt * 8 + 2 * tg;
                float2 bb = *(const float2*)&bias[n];
                float v0 = acc[mt][nt][half * 2 + 0] + bb.x;
                float v1 = acc[mt][nt][half * 2 + 1] + bb.y;
                if (split) {
                    const int b = m >> 11, s = m & 2047;
                    const int h = n >> 6, d = n & 63;
                    *(float2*)&C[(((size_t)(b * Hc + h)) * Sc + s) * Dc + d] =
                        make_float2(v0, v1);
                } else {
                    *(float2*)&C[(size_t)m * Ec + n] = make_float2(v0, v1);
                }
            }
        }
    }
}

// ---------------- Flash attention (tf32 mma, P in regs, cp.async) ----------
// 128 q / CTA, 8 warps. Raw f32 smem: Q[128][68], K[2][64][68], V[2][64][72].
// S-MMA B rows permuted by pi(n)=(n>>1)+4(n&1) so the S accumulator is
// directly the PV A-fragment (P never stored).
#define AQ 128
#define QST 68
#define KST 68
#define VST 72
#define KSTG (64*KST)   // 4352
#define VSTG (64*VST)   // 4608
#define ASM_W (128*QST + 2*KSTG + 2*VSTG)   // 26624 words = 106496 B

__global__ __launch_bounds__(256, 2) void attn_tc(
    const float* __restrict__ Qg_, const float* __restrict__ Kg_,
    const float* __restrict__ Vg_, float* __restrict__ Ag_)
{
    extern __shared__ float smf[];
    float* Qs = smf;                       // [128][68]
    float* Kb = smf + 128 * QST;           // 2 x [64][68]
    float* Vb = Kb + 2 * KSTG;             // 2 x [64][72]

    const int tid  = threadIdx.x;
    const int lane = tid & 31, warp = tid >> 5;
    const int g = lane >> 2, tg = lane & 3;
    const int q0 = warp * 16;
    const int pig = (g >> 1) + 4 * (g & 1);

    const int qt = blockIdx.x, h = blockIdx.y, b = blockIdx.z;
    const size_t headOff = ((size_t)(b * Hc + h)) * Sc * Dc;
    const float* Qg = Qg_ + headOff + (size_t)qt * AQ * Dc;
    const float* Kg = Kg_ + headOff;
    const float* Vg = Vg_ + headOff;

    // copy mappings
    const int qr = tid >> 1, qc = (tid & 1) * 32;          // Q: 8 chunks
    const int kr = tid >> 2, kc = (tid & 3) * 4;           // K/V: 4 chunks (stride 16 words)
    const uint32_t sQ = (uint32_t)__cvta_generic_to_shared(Qs) + (qr * QST + qc) * 4;
    const uint32_t sK = (uint32_t)__cvta_generic_to_shared(Kb) + (kr * KST + kc) * 4;
    const uint32_t sV = (uint32_t)__cvta_generic_to_shared(Vb) + (kr * VST + kc) * 4;
    const float* Kgr = Kg + (size_t)kr * Dc + kc;
    const float* Vgr = Vg + (size_t)kr * Dc + kc;

    // prologue: Q + tile 0 (one group)
    #pragma unroll
    for (int j = 0; j < 8; j++) cpa16(sQ + 16 * j, Qg + (size_t)qr * Dc + qc + 4 * j);
    #pragma unroll
    for (int j = 0; j < 4; j++) cpa16(sK + 64 * j, Kgr + 16 * j);
    #pragma unroll
    for (int j = 0; j < 4; j++) cpa16(sV + 64 * j, Vgr + 16 * j);
    cp_commit();

    float o[8][4];
    float mrow[2], lrow[2];
    #pragma unroll
    for (int nt = 0; nt < 8; nt++)
        #pragma unroll
        for (int i = 0; i < 4; i++) o[nt][i] = 0.f;
    mrow[0] = mrow[1] = -INFINITY;
    lrow[0] = lrow[1] = 0.f;

    const int NT = Sc / 64;   // 32
    for (int kt = 0; kt < NT; kt++) {
        const int p = kt & 1;
        if (kt + 1 < NT) {
            const size_t off = (size_t)(kt + 1) * 64 * Dc;
            const uint32_t dK = sK + (1 - p) * KSTG * 4;
            const uint32_t dV = sV + (1 - p) * VSTG * 4;
            #pragma unroll
            for (int j = 0; j < 4; j++) cpa16(dK + 64 * j, Kgr + off + 16 * j);
            #pragma unroll
            for (int j = 0; j < 4; j++) cpa16(dV + 64 * j, Vgr + off + 16 * j);
            cp_commit();
            cp_wait1();
        } else {
            cp_wait0();
        }
        __syncthreads();

        const float* Ks = Kb + p * KSTG;
        const float* Vs = Vb + p * VSTG;

        // S = Q K^T (B rows taken at 8nt + pig)
        float s[8][4];
        #pragma unroll
        for (int nt = 0; nt < 8; nt++)
            #pragma unroll
            for (int i = 0; i < 4; i++) s[nt][i] = 0.f;

        #pragma unroll
        for (int ks = 0; ks < 8; ks++) {
            uint32_t af[4];
            af[0] = f2tf(Qs[(q0 + g) * QST + ks * 8 + tg]);
            af[1] = f2tf(Qs[(q0 + 8 + g) * QST + ks * 8 + tg]);
            af[2] = f2tf(Qs[(q0 + g) * QST + ks * 8 + tg + 4]);
            af[3] = f2tf(Qs[(q0 + 8 + g) * QST + ks * 8 + tg + 4]);
            #pragma unroll
            for (int nt = 0; nt < 8; nt++) {
                const float* kp = Ks + (nt * 8 + pig) * KST;
                uint32_t bf[2];
                bf[0] = f2tf(kp[ks * 8 + tg]);
                bf[1] = f2tf(kp[ks * 8 + tg + 4]);
                mma8(s[nt], af, bf);
            }
        }
        // thread holds S(q0+g+8h, kv=8nt+tg) in s[nt][2h], kv=8nt+tg+4 in s[nt][2h+1]

        // Online softmax (scale 0.125 applied here; rows spread over 4-lane quad)
        #pragma unroll
        for (int half = 0; half < 2; half++) {
            float tmax = -INFINITY;
            #pragma unroll
            for (int nt = 0; nt < 8; nt++) {
                s[nt][half * 2 + 0] *= 0.125f;
                s[nt][half * 2 + 1] *= 0.125f;
                tmax = fmaxf(tmax, s[nt][half * 2 + 0]);
                tmax = fmaxf(tmax, s[nt][half * 2 + 1]);
            }
            tmax = fmaxf(tmax, __shfl_xor_sync(0xffffffffu, tmax, 1));
            tmax = fmaxf(tmax, __shfl_xor_sync(0xffffffffu, tmax, 2));
            const float mn   = fmaxf(mrow[half], tmax);
            const float corr = __expf(mrow[half] - mn);
            float rs = 0.f;
            #pragma unroll
            for (int nt = 0; nt < 8; nt++) {
                float p0 = __expf(s[nt][half * 2 + 0] - mn);
                float p1 = __expf(s[nt][half * 2 + 1] - mn);
                s[nt][half * 2 + 0] = p0;
                s[nt][half * 2 + 1] = p1;
                rs += p0 + p1;
                o[nt][half * 2 + 0] *= corr;
                o[nt][half * 2 + 1] *= corr;
            }
            rs += __shfl_xor_sync(0xffffffffu, rs, 1);
            rs += __shfl_xor_sync(0xffffffffu, rs, 2);
            lrow[half] = lrow[half] * corr + rs;
            mrow[half] = mn;
        }

        // O += P @ V : P fragments straight from S accumulator
        #pragma unroll
        for (int ks = 0; ks < 8; ks++) {
            uint32_t af[4];
            af[0] = f2tf(s[ks][0]);
            af[1] = f2tf(s[ks][2]);
            af[2] = f2tf(s[ks][1]);
            af[3] = f2tf(s[ks][3]);
            const float* v0 = Vs + (ks * 8 + tg) * VST;
            const float* v1 = Vs + (ks * 8 + tg + 4) * VST;
            #pragma unroll
            for (int nt = 0; nt < 8; nt++) {
                uint32_t bf[2];
                bf[0] = f2tf(v0[nt * 8 + g]);
                bf[1] = f2tf(v1[nt * 8 + g]);
                mma8(o[nt], af, bf);
            }
        }
        __syncthreads();   // all warps done with buf p before next prefetch overwrites it
    }

    // Epilogue: normalize, write concat layout [B,S,E]
    #pragma unroll
    for (int half = 0; half < 2; half++) {
        const float inv = 1.f / lrow[half];
        const int q = qt * AQ + q0 + g + half * 8;
        #pragma unroll
        for (int nt = 0; nt < 8; nt++) {
            const int d = nt * 8 + 2 * tg;
            *(float2*)&Ag_[((size_t)b * Sc + q) * Ec + h * Dc + d] =
                make_float2(o[nt][half * 2 + 0] * inv, o[nt][half * 2 + 1] * inv);
        }
    }
}

// ---------------------------------------------------------------------------
extern "C" void kernel_launch(void* const* d_in, const int* in_sizes, int n_in,
                              void* d_out, int out_size)
{
    const float* x  = (const float*)d_in[0];
    const float* Wq = (const float*)d_in[1];
    const float* bq = (const float*)d_in[2];
    const float* Wk = (const float*)d_in[3];
    const float* bk = (const float*)d_in[4];
    const float* Wv = (const float*)d_in[5];
    const float* bv = (const float*)d_in[6];
    const float* Wo = (const float*)d_in[7];
    const float* bo = (const float*)d_in[8];
    float* out = (float*)d_out;

    float *pQ, *pK, *pV, *pA;
    cudaGetSymbolAddress((void**)&pQ, g_Q);
    cudaGetSymbolAddress((void**)&pK, g_K);
    cudaGetSymbolAddress((void**)&pV, g_V);
    cudaGetSymbolAddress((void**)&pA, g_A);

    const int gemmSmem = GSM * 4;      // 71680 B
    const int attnSmem = ASM_W * 4;    // 106496 B
    cudaFuncSetAttribute(gemm_tc, cudaFuncAttributeMaxDynamicSharedMemorySize, gemmSmem);
    cudaFuncSetAttribute(attn_tc, cudaFuncAttributeMaxDynamicSharedMemorySize, attnSmem);

    dim3 gg(Ec / GBN, Mtot / GBM);   // (8, 64)
    gemm_tc<<<gg, 256, gemmSmem>>>(x, Wq, bq, pQ, 1);
    gemm_tc<<<gg, 256, gemmSmem>>>(x, Wk, bk, pK, 1);
    gemm_tc<<<gg, 256, gemmSmem>>>(x, Wv, bv, pV, 1);
    attn_tc<<<dim3(Sc / AQ, Hc, Bc), 256, attnSmem>>>(pQ, pK, pV, pA);
    gemm_tc<<<gg, 256, gemmSmem>>>(pA, Wo, bo, out, 0);
}